// round 10
// baseline (speedup 1.0000x reference)
#include <cuda_runtime.h>
#include <cuda_bf16.h>
#include <cstdint>

#define DN 256
#define HN 64
#define BN 8192
#define ROWS 32
#define THREADS 128
#define NBLOCKS (BN / ROWS)   // 256  -> 2 CTAs per SM

// smem byte layout
#define ZSTRB 528             // z plane row stride (264 bf16)
#define Z_H_OFF 0             // zh [32 rows][264] bf16
#define Z_L_OFF 16896         // zl
#define WT_OFF  33792         // weight ring: 3 bufs x (2 planes x 64h x 144B)
#define WT_BUF  18432
#define WT_PLANE 9216
#define RED_OFF 89088         // [2][32] f32
#define B1S_OFF 89344         // 64 f32
#define W2S_OFF 89600         // 64 f32
#define SMEM_TOTAL 89856

typedef unsigned long long u64;

// Streaming weight tiles: [i][chunk 4][plane 2][h 64][j 64] bf16 (16.8 MB, L2-resident)
__device__ __align__(256) __nv_bfloat16 g_Wc[(size_t)DN * 4 * 2 * 64 * 64];

// ---------------- helpers ----------------
__device__ __forceinline__ uint32_t smem_u32(const void* p) {
    uint32_t a;
    asm("{ .reg .u64 t; cvta.to.shared.u64 t, %1; cvt.u32.u64 %0, t; }"
        : "=r"(a) : "l"(p));
    return a;
}
__device__ __forceinline__ void cp16(uint32_t sdst, const void* g) {
    asm volatile("cp.async.cg.shared.global [%0], [%1], 16;"
                 :: "r"(sdst), "l"(g) : "memory");
}
#define CP_COMMIT() asm volatile("cp.async.commit_group;" ::: "memory")
#define CP_WAIT1()  asm volatile("cp.async.wait_group 1;" ::: "memory")

__device__ __forceinline__ void ldsm4(uint32_t* r, uint32_t a) {
    asm volatile("ldmatrix.sync.aligned.m8n8.x4.shared.b16 {%0,%1,%2,%3}, [%4];"
                 : "=r"(r[0]), "=r"(r[1]), "=r"(r[2]), "=r"(r[3]) : "r"(a));
}
__device__ __forceinline__ void mma_bf16(float* c, const uint32_t* a,
                                         uint32_t b0, uint32_t b1) {
    asm volatile(
        "mma.sync.aligned.m16n8k16.row.col.f32.bf16.bf16.f32 "
        "{%0,%1,%2,%3}, {%4,%5,%6,%7}, {%8,%9}, {%0,%1,%2,%3};"
        : "+f"(c[0]), "+f"(c[1]), "+f"(c[2]), "+f"(c[3])
        : "r"(a[0]), "r"(a[1]), "r"(a[2]), "r"(a[3]), "r"(b0), "r"(b1));
}
__device__ __forceinline__ int nch_of(int i) {
    return ((((i + 15) & ~15) + 63) >> 6);
}
__device__ __forceinline__ uint32_t wt_dst(int p) {
    return (uint32_t)((p >> 9) * WT_PLANE + ((p >> 3) & 63) * 144 + (p & 7) * 16);
}

// ---------------- precompute: mask + bf16 hi/lo tile images ----------------
__global__ void precompute_kernel(const float* __restrict__ W1,
                                  const float* __restrict__ adj_logits) {
    int i = blockIdx.x;
    __shared__ float asig[DN];
    for (int j = threadIdx.x; j < DN; j += blockDim.x) {
        float l = adj_logits[j * DN + i];
        float s = 1.0f / (1.0f + __expf(-l));
        asig[j] = (j == i) ? 0.0f : s;
    }
    __syncthreads();
    const float* W1i = W1 + (size_t)i * HN * DN;
    for (int idx = threadIdx.x; idx < HN * DN; idx += blockDim.x) {
        int k = idx >> 8, j = idx & 255;
        float w = W1i[idx] * asig[j];
        __nv_bfloat16 hi = __float2bfloat16(w);
        __nv_bfloat16 lo = __float2bfloat16(w - __bfloat162float(hi));
        size_t o = ((size_t)i * 4 + (j >> 6)) * 8192 + (size_t)k * 64 + (j & 63);
        g_Wc[o]        = hi;   // plane 0
        g_Wc[o + 4096] = lo;   // plane 1
    }
}

// ---------------- main kernel ----------------
// Warp grid (4 warps): wm = wid&1 -> m-tile (16 rows), wn = wid>>1 -> n-half (32 h)
extern __shared__ char smem[];

__global__ void __launch_bounds__(THREADS, 2)
scm_mma_kernel(const float* __restrict__ noise,
               const float* __restrict__ b1,
               const float* __restrict__ W2,
               const float* __restrict__ b2,
               const float* __restrict__ log_sigma,
               float* __restrict__ out) {
    const uint32_t sb = smem_u32(smem);
    const int tid = threadIdx.x, lane = tid & 31, wid = tid >> 5;
    const int wm = wid & 1, wn = wid >> 1;
    const int m0 = wm * 16, h0 = wn * 32;
    const int row0 = blockIdx.x * ROWS;
    float* b1s = (float*)(smem + B1S_OFF);
    float* w2s = (float*)(smem + W2S_OFF);
    float* red = (float*)(smem + RED_OFF);

    // zero z planes (33792 B)
    for (int idx = tid; idx < 33792 / 8; idx += THREADS) ((u64*)smem)[idx] = 0ull;
    __syncthreads();

    const uint32_t a_lane = (uint32_t)(m0 + (lane & 15)) * ZSTRB
                          + (((lane >> 4) & 1) << 4);
    const uint32_t zh_base = sb + Z_H_OFF + a_lane;
    const uint32_t zl_base = sb + Z_L_OFF + a_lane;
    const uint32_t b_lane = (uint32_t)(h0 + ((lane >> 4) << 3) + (lane & 7)) * 144
                          + (((lane >> 3) & 1) << 4);

    // prime ring: tile (1,0) -> slot 0, tile (2,0) -> slot 1
    {
        const char* g1 = (const char*)g_Wc + (size_t)4 * 16384;
        int p = tid;
        #pragma unroll
        for (int n = 0; n < 8; ++n, p += THREADS)
            cp16(sb + WT_OFF + wt_dst(p), g1 + (size_t)p * 16);
        CP_COMMIT();
        const char* g2 = (const char*)g_Wc + (size_t)8 * 16384;
        p = tid;
        #pragma unroll
        for (int n = 0; n < 8; ++n, p += THREADS)
            cp16(sb + WT_OFF + WT_BUF + wt_dst(p), g2 + (size_t)p * 16);
        CP_COMMIT();
    }
    int pi = 3, pc = 0;        // generator past (1,0),(2,0)
    int np_slot = 2, cs = 0;

    for (int i = 0; i < DN; ++i) {
        const int kpad = (i + 15) & ~15;
        const int nchk = (kpad + 63) >> 6;   // 0 for i==0

        // stage per-node params
        if (tid < 64)       b1s[tid]      = b1[i * HN + tid];
        else                w2s[tid - 64] = W2[i * HN + tid - 64];
        float nv = 0.f, b2v = 0.f, sigv = 0.f;
        if (tid < ROWS) {
            nv   = __ldg(noise + (size_t)(row0 + tid) * DN + i);
            b2v  = __ldg(b2 + i);
            sigv = __expf(__ldg(log_sigma + i));
        }
        float acc[4][4] = {}, acc2[4][4] = {};
        if (nchk == 0) __syncthreads();     // publish staging (i == 0 only)

        for (int c = 0; c < nchk; ++c) {
            CP_WAIT1();          // oldest outstanding group (this tile) done
            __syncthreads();     // tile visible; z col i-1 published (c==0)

            if (pi < DN) {       // prefetch 2-ahead into np_slot
                const char* g = (const char*)g_Wc + ((size_t)pi * 4 + pc) * 16384;
                uint32_t bbase = sb + WT_OFF + (uint32_t)np_slot * WT_BUF;
                int p = tid;
                #pragma unroll
                for (int n = 0; n < 8; ++n, p += THREADS)
                    cp16(bbase + wt_dst(p), g + (size_t)p * 16);
                pc++; if (pc >= nch_of(pi)) { pi++; pc = 0; }
                np_slot = (np_slot == 2) ? 0 : np_slot + 1;
            }
            CP_COMMIT();

            const uint32_t wb = sb + WT_OFF + (uint32_t)cs * WT_BUF + b_lane;
            cs = (cs == 2) ? 0 : cs + 1;
            const int jcend = min(kpad - 64 * c, 64);

            auto do_slice = [&](int jc, float (*ac)[4]) {
                const uint32_t jg2 = (uint32_t)(64 * c + jc) * 2;
                uint32_t ah[4], al[4], bh[8], bl[8];
                ldsm4(ah, zh_base + jg2);
                ldsm4(al, zl_base + jg2);
                ldsm4(bh,     wb + jc * 2);
                ldsm4(bh + 4, wb + 2304 + jc * 2);
                ldsm4(bl,     wb + WT_PLANE + jc * 2);
                ldsm4(bl + 4, wb + WT_PLANE + 2304 + jc * 2);
                #pragma unroll
                for (int nt = 0; nt < 4; ++nt) {
                    mma_bf16(ac[nt], ah, bh[2 * nt], bh[2 * nt + 1]);  // hh
                    mma_bf16(ac[nt], ah, bl[2 * nt], bl[2 * nt + 1]);  // hl
                    mma_bf16(ac[nt], al, bh[2 * nt], bh[2 * nt + 1]);  // lh
                }
            };
            #pragma unroll 2
            for (int jc = 0; jc < jcend; jc += 32) {
                do_slice(jc, acc);
                if (jc + 16 < jcend) do_slice(jc + 16, acc2);
            }
        }

        // epilogue: merge acc banks, silu + dot(w2), quad reduce, cross-half red
        float s_lo = 0.f, s_hi = 0.f;
        #pragma unroll
        for (int nt = 0; nt < 4; ++nt) {
            int hc = h0 + 8 * nt + 2 * (lane & 3);
            float ba = b1s[hc], bbv = b1s[hc + 1];
            float wa = w2s[hc], wbv = w2s[hc + 1];
            float x;
            x = acc[nt][0] + acc2[nt][0] + ba;
            s_lo += __fdividef(x, 1.f + __expf(-x)) * wa;
            x = acc[nt][1] + acc2[nt][1] + bbv;
            s_lo += __fdividef(x, 1.f + __expf(-x)) * wbv;
            x = acc[nt][2] + acc2[nt][2] + ba;
            s_hi += __fdividef(x, 1.f + __expf(-x)) * wa;
            x = acc[nt][3] + acc2[nt][3] + bbv;
            s_hi += __fdividef(x, 1.f + __expf(-x)) * wbv;
        }
        s_lo += __shfl_xor_sync(0xffffffffu, s_lo, 1);
        s_lo += __shfl_xor_sync(0xffffffffu, s_lo, 2);
        s_hi += __shfl_xor_sync(0xffffffffu, s_hi, 1);
        s_hi += __shfl_xor_sync(0xffffffffu, s_hi, 2);
        if ((lane & 3) == 0) {
            red[wn * 32 + m0 + (lane >> 2)]     = s_lo;
            red[wn * 32 + m0 + 8 + (lane >> 2)] = s_hi;
        }
        __syncthreads();

        if (tid < ROWS) {
            float val = red[tid] + red[32 + tid] + b2v + sigv * nv;
            __nv_bfloat16 zh = __float2bfloat16(val);
            __nv_bfloat16 zl = __float2bfloat16(val - __bfloat162float(zh));
            *(__nv_bfloat16*)(smem + Z_H_OFF + tid * ZSTRB + i * 2) = zh;
            *(__nv_bfloat16*)(smem + Z_L_OFF + tid * ZSTRB + i * 2) = zl;
        }
        // next node's chunk-0 sync publishes z col i
    }

    __syncthreads();   // publish final z columns
    // coalesced output: out = zh + zl
    for (int idx = tid; idx < ROWS * DN; idx += THREADS) {
        int r = idx >> 8, j = idx & 255;
        float zh = __bfloat162float(
            *(const __nv_bfloat16*)(smem + Z_H_OFF + r * ZSTRB + j * 2));
        float zl = __bfloat162float(
            *(const __nv_bfloat16*)(smem + Z_L_OFF + r * ZSTRB + j * 2));
        out[(size_t)(row0 + r) * DN + j] = zh + zl;
    }
}

extern "C" void kernel_launch(void* const* d_in, const int* in_sizes, int n_in,
                              void* d_out, int out_size) {
    const float* noise      = (const float*)d_in[0];
    const float* adj_logits = (const float*)d_in[1];
    const float* W1         = (const float*)d_in[2];
    const float* b1         = (const float*)d_in[3];
    const float* W2         = (const float*)d_in[4];
    const float* b2         = (const float*)d_in[5];
    const float* log_sigma  = (const float*)d_in[6];
    float* out = (float*)d_out;

    precompute_kernel<<<DN, 256>>>(W1, adj_logits);

    cudaFuncSetAttribute(scm_mma_kernel, cudaFuncAttributeMaxDynamicSharedMemorySize,
                         SMEM_TOTAL);
    scm_mma_kernel<<<NBLOCKS, THREADS, SMEM_TOTAL>>>(noise, b1, W2, b2,
                                                     log_sigma, out);
}

// round 12
// speedup vs baseline: 1.1152x; 1.1152x over previous
#include <cuda_runtime.h>
#include <cuda_bf16.h>
#include <cstdint>

#define DN 256
#define HN 64
#define BN 8192
#define ROWS 64
#define THREADS 384           // 8 MMA warps (0-255) + 4 epilogue warps (256-383)
#define NBLOCKS (BN / ROWS)   // 128

// smem byte layout
#define ZSTRB 528             // z plane row stride (264 bf16)
#define Z_H_OFF 0
#define Z_L_OFF 33792
#define WT_OFF  67584         // ring: 3 x 18432
#define WT_BUF  18432
#define WT_PLANE 9216
#define D_OFF   122880        // D tile: [2][64][68] f32 = 2 x 17408
#define D_STR   68
#define MBAR_OFF 157696       // d0,d1 (at +0,+8), z0,z1 (at +16,+24)
#define SMEM_TOTAL 157760

typedef unsigned long long u64;

__device__ __align__(256) __nv_bfloat16 g_Wc[(size_t)DN * 4 * 2 * 64 * 64];

// ---------------- helpers ----------------
__device__ __forceinline__ uint32_t smem_u32(const void* p) {
    uint32_t a;
    asm("{ .reg .u64 t; cvta.to.shared.u64 t, %1; cvt.u32.u64 %0, t; }"
        : "=r"(a) : "l"(p));
    return a;
}
__device__ __forceinline__ void cp16(uint32_t sdst, const void* g) {
    asm volatile("cp.async.cg.shared.global [%0], [%1], 16;"
                 :: "r"(sdst), "l"(g) : "memory");
}
#define CP_COMMIT() asm volatile("cp.async.commit_group;" ::: "memory")
#define CP_WAIT1()  asm volatile("cp.async.wait_group 1;" ::: "memory")
#define BAR_MMA()   asm volatile("bar.sync 1, 256;" ::: "memory")
#define MBAR_INIT(mb, c) asm volatile("mbarrier.init.shared.b64 [%0], %1;" :: "r"(mb), "r"(c) : "memory")
#define MBAR_ARRIVE(mb)  asm volatile("mbarrier.arrive.shared.b64 _, [%0];" :: "r"(mb) : "memory")

__device__ __forceinline__ void mbar_wait(uint32_t mb, uint32_t parity) {
    asm volatile(
        "{ .reg .pred P;\n\t"
        "WL_%=:\n\t"
        "mbarrier.try_wait.parity.acquire.cta.shared::cta.b64 P, [%0], %1, 0x989680;\n\t"
        "@P bra.uni WD_%=;\n\t"
        "bra.uni WL_%=;\n\t"
        "WD_%=: }"
        :: "r"(mb), "r"(parity) : "memory");
}
__device__ __forceinline__ void ldsm4(uint32_t* r, uint32_t a) {
    asm volatile("ldmatrix.sync.aligned.m8n8.x4.shared.b16 {%0,%1,%2,%3}, [%4];"
                 : "=r"(r[0]), "=r"(r[1]), "=r"(r[2]), "=r"(r[3]) : "r"(a));
}
__device__ __forceinline__ void mma_bf16(float* c, const uint32_t* a,
                                         uint32_t b0, uint32_t b1) {
    asm volatile(
        "mma.sync.aligned.m16n8k16.row.col.f32.bf16.bf16.f32 "
        "{%0,%1,%2,%3}, {%4,%5,%6,%7}, {%8,%9}, {%0,%1,%2,%3};"
        : "+f"(c[0]), "+f"(c[1]), "+f"(c[2]), "+f"(c[3])
        : "r"(a[0]), "r"(a[1]), "r"(a[2]), "r"(a[3]), "r"(b0), "r"(b1));
}
__device__ __forceinline__ int nch_of(int i) {
    return ((((i + 15) & ~15) + 63) >> 6);
}
__device__ __forceinline__ uint32_t wt_dst(int p) {
    return (uint32_t)((p >> 9) * WT_PLANE + ((p >> 3) & 63) * 144 + (p & 7) * 16);
}
__device__ __forceinline__ float silu(float x) {
    return __fdividef(x, 1.0f + __expf(-x));
}

// ---------------- precompute (unchanged, proven) ----------------
__global__ void precompute_kernel(const float* __restrict__ W1,
                                  const float* __restrict__ adj_logits) {
    int i = blockIdx.x;
    __shared__ float asig[DN];
    for (int j = threadIdx.x; j < DN; j += blockDim.x) {
        float l = adj_logits[j * DN + i];
        float s = 1.0f / (1.0f + __expf(-l));
        asig[j] = (j == i) ? 0.0f : s;
    }
    __syncthreads();
    const float* W1i = W1 + (size_t)i * HN * DN;
    for (int idx = threadIdx.x; idx < HN * DN; idx += blockDim.x) {
        int k = idx >> 8, j = idx & 255;
        float w = W1i[idx] * asig[j];
        __nv_bfloat16 hi = __float2bfloat16(w);
        __nv_bfloat16 lo = __float2bfloat16(w - __bfloat162float(hi));
        size_t o = ((size_t)i * 4 + (j >> 6)) * 8192 + (size_t)k * 64 + (j & 63);
        g_Wc[o]        = hi;
        g_Wc[o + 4096] = lo;
    }
}

// ---------------- main kernel ----------------
extern __shared__ char smem[];

__global__ void __launch_bounds__(THREADS, 1)
scm_mma_kernel(const float* __restrict__ noise,
               const float* __restrict__ b1,
               const float* __restrict__ W2,
               const float* __restrict__ b2,
               const float* __restrict__ log_sigma,
               float* __restrict__ out) {
    const uint32_t sb = smem_u32(smem);
    const int tid = threadIdx.x, lane = tid & 31, wid = tid >> 5;
    const int row0 = blockIdx.x * ROWS;
    float* Dbuf = (float*)(smem + D_OFF);
    const uint32_t mb_d0 = sb + MBAR_OFF, mb_z0 = sb + MBAR_OFF + 16;

    // init: zero z planes, init mbarriers
    for (int idx = tid; idx < 67584 / 8; idx += THREADS) ((u64*)smem)[idx] = 0ull;
    if (tid == 0) {
        MBAR_INIT(mb_d0, 256);  MBAR_INIT(mb_d0 + 8, 256);
        MBAR_INIT(mb_z0, 128);  MBAR_INIT(mb_z0 + 8, 128);
    }
    __syncthreads();

    if (wid < 8) {
        // ================= MMA warps =================
        const int wm = wid & 3, wn = wid >> 2;
        const int m0 = wm * 16, h0 = wn * 32;
        const uint32_t a_lane = (uint32_t)(m0 + (lane & 15)) * ZSTRB
                              + (((lane >> 4) & 1) << 4);
        const uint32_t zh_base = sb + Z_H_OFF + a_lane;
        const uint32_t zl_base = sb + Z_L_OFF + a_lane;
        const uint32_t b_lane = (uint32_t)(h0 + ((lane >> 4) << 3) + (lane & 7)) * 144
                              + (((lane >> 3) & 1) << 4);

        // prime ring: tiles (1,0) and (2,0)
        {
            const char* g1 = (const char*)g_Wc + (size_t)4 * 16384;
            int p = tid;
            #pragma unroll
            for (int n = 0; n < 4; ++n, p += 256)
                cp16(sb + WT_OFF + wt_dst(p), g1 + (size_t)p * 16);
            CP_COMMIT();
            const char* g2 = (const char*)g_Wc + (size_t)8 * 16384;
            p = tid;
            #pragma unroll
            for (int n = 0; n < 4; ++n, p += 256)
                cp16(sb + WT_OFF + WT_BUF + wt_dst(p), g2 + (size_t)p * 16);
            CP_COMMIT();
        }
        int pi = 3, pc = 0, np_slot = 2, cs = 0;
        int ph_z[2] = {0, 0};     // explicit per-slot z-barrier phase cursors

        for (int i = 1; i < DN; ++i) {
            const int kpad = (i + 15) & ~15;
            const int nchk = (kpad + 63) >> 6;
            float acc[4][4] = {}, acc2[4][4] = {};

            for (int c = 0; c < nchk; ++c) {
                CP_WAIT1();
                BAR_MMA();           // tile (i,c) visible to all MMA warps

                if (pi < DN) {       // prefetch 2-ahead
                    const char* g = (const char*)g_Wc + ((size_t)pi * 4 + pc) * 16384;
                    uint32_t bbase = sb + WT_OFF + (uint32_t)np_slot * WT_BUF;
                    int p = tid;
                    #pragma unroll
                    for (int n = 0; n < 4; ++n, p += 256)
                        cp16(bbase + wt_dst(p), g + (size_t)p * 16);
                    pc++; if (pc >= nch_of(pi)) { pi++; pc = 0; }
                    np_slot = (np_slot == 2) ? 0 : np_slot + 1;
                }
                CP_COMMIT();

                const uint32_t wb = sb + WT_OFF + (uint32_t)cs * WT_BUF + b_lane;
                cs = (cs == 2) ? 0 : cs + 1;
                const int jcend = min(kpad - 64 * c, 64);

                for (int jc = 0; jc < jcend; jc += 16) {
                    if (64 * c + jc == kpad - 16) {        // final slice: needs z_{i-1}
                        const int zs = (i - 1) & 1;
                        mbar_wait(mb_z0 + zs * 8, ph_z[zs]);
                        ph_z[zs] ^= 1;
                    }
                    float (*ac)[4] = ((jc >> 4) & 1) ? acc2 : acc;
                    const uint32_t jg2 = (uint32_t)(64 * c + jc) * 2;
                    uint32_t ah[4], al[4], bh[8], bl[8];
                    ldsm4(ah, zh_base + jg2);
                    ldsm4(al, zl_base + jg2);
                    ldsm4(bh,     wb + jc * 2);
                    ldsm4(bh + 4, wb + 2304 + jc * 2);
                    ldsm4(bl,     wb + WT_PLANE + jc * 2);
                    ldsm4(bl + 4, wb + WT_PLANE + 2304 + jc * 2);
                    #pragma unroll
                    for (int nt = 0; nt < 4; ++nt) {
                        mma_bf16(ac[nt], ah, bh[2 * nt], bh[2 * nt + 1]);  // hh
                        mma_bf16(ac[nt], ah, bl[2 * nt], bl[2 * nt + 1]);  // hl
                        mma_bf16(ac[nt], al, bh[2 * nt], bh[2 * nt + 1]);  // lh
                    }
                }
            }

            // store merged D tile to slot i&1, hand off to epilogue warps
            float* Dp = Dbuf + (size_t)(i & 1) * 64 * D_STR;
            const int r = m0 + (lane >> 2);
            #pragma unroll
            for (int nt = 0; nt < 4; ++nt) {
                const int col = h0 + 8 * nt + 2 * (lane & 3);
                float2 v0 = make_float2(acc[nt][0] + acc2[nt][0],
                                        acc[nt][1] + acc2[nt][1]);
                float2 v1 = make_float2(acc[nt][2] + acc2[nt][2],
                                        acc[nt][3] + acc2[nt][3]);
                *(float2*)(Dp + r * D_STR + col)       = v0;
                *(float2*)(Dp + (r + 8) * D_STR + col) = v1;
            }
            MBAR_ARRIVE(mb_d0 + (i & 1) * 8);
        }
    } else {
        // ================= Epilogue warps =================
        const int eid  = tid - 256;          // 0..127
        const int row  = eid >> 1;           // batch row 0..63
        const int half = eid & 1;            // hidden half
        const int h0e  = half * 32;
        int ph_d[2] = {0, 0};                // explicit per-slot d-barrier cursors

        for (int i = 0; i < DN; ++i) {
            float b2v  = __ldg(b2 + i);
            float sigv = __expf(__ldg(log_sigma + i));
            float nv   = (half == 0)
                       ? __ldg(noise + (size_t)(row0 + row) * DN + i) : 0.0f;
            float4 b1q[8], w2q[8];
            #pragma unroll
            for (int k = 0; k < 8; ++k) {
                b1q[k] = __ldg((const float4*)(b1 + i * HN + h0e + 4 * k));
                w2q[k] = __ldg((const float4*)(W2 + i * HN + h0e + 4 * k));
            }

            float s = 0.0f;
            if (i > 0) {
                const int ds = i & 1;
                mbar_wait(mb_d0 + ds * 8, ph_d[ds]);
                ph_d[ds] ^= 1;
                const float* Dp = Dbuf + (size_t)(i & 1) * 64 * D_STR
                                + row * D_STR + h0e;
                #pragma unroll
                for (int k = 0; k < 8; ++k) {
                    float4 dv = *(const float4*)(Dp + 4 * k);
                    s += silu(dv.x + b1q[k].x) * w2q[k].x;
                    s += silu(dv.y + b1q[k].y) * w2q[k].y;
                    s += silu(dv.z + b1q[k].z) * w2q[k].z;
                    s += silu(dv.w + b1q[k].w) * w2q[k].w;
                }
            } else {
                #pragma unroll
                for (int k = 0; k < 8; ++k) {
                    s += silu(b1q[k].x) * w2q[k].x;
                    s += silu(b1q[k].y) * w2q[k].y;
                    s += silu(b1q[k].z) * w2q[k].z;
                    s += silu(b1q[k].w) * w2q[k].w;
                }
            }
            s += __shfl_xor_sync(0xffffffffu, s, 1);   // combine hidden halves
            if (half == 0) {
                float val = s + b2v + sigv * nv;
                __nv_bfloat16 zh = __float2bfloat16(val);
                __nv_bfloat16 zl = __float2bfloat16(val - __bfloat162float(zh));
                *(__nv_bfloat16*)(smem + Z_H_OFF + row * ZSTRB + i * 2) = zh;
                *(__nv_bfloat16*)(smem + Z_L_OFF + row * ZSTRB + i * 2) = zl;
            }
            MBAR_ARRIVE(mb_z0 + (i & 1) * 8);
        }
    }

    __syncthreads();   // all z columns final
    // coalesced output: out = zh + zl
    for (int idx = tid; idx < ROWS * DN; idx += THREADS) {
        int r = idx >> 8, j = idx & 255;
        float zh = __bfloat162float(
            *(const __nv_bfloat16*)(smem + Z_H_OFF + r * ZSTRB + j * 2));
        float zl = __bfloat162float(
            *(const __nv_bfloat16*)(smem + Z_L_OFF + r * ZSTRB + j * 2));
        out[(size_t)(row0 + r) * DN + j] = zh + zl;
    }
}

extern "C" void kernel_launch(void* const* d_in, const int* in_sizes, int n_in,
                              void* d_out, int out_size) {
    const float* noise      = (const float*)d_in[0];
    const float* adj_logits = (const float*)d_in[1];
    const float* W1         = (const float*)d_in[2];
    const float* b1         = (const float*)d_in[3];
    const float* W2         = (const float*)d_in[4];
    const float* b2         = (const float*)d_in[5];
    const float* log_sigma  = (const float*)d_in[6];
    float* out = (float*)d_out;

    precompute_kernel<<<DN, 256>>>(W1, adj_logits);

    cudaFuncSetAttribute(scm_mma_kernel, cudaFuncAttributeMaxDynamicSharedMemorySize,
                         SMEM_TOTAL);
    scm_mma_kernel<<<NBLOCKS, THREADS, SMEM_TOTAL>>>(noise, b1, W2, b2,
                                                     log_sigma, out);
}